// round 1
// baseline (speedup 1.0000x reference)
#include <cuda_runtime.h>
#include <cstddef>

#define BB 4
#define SS 4096
#define DH 64
#define BM 64
#define BN 64
#define DP 68          // padded row length (floats), multiple of 4 for float4 alignment
#define NT 256

// scratch: inverse row sums for the weights-normalization pass (no cudaMalloc allowed)
__device__ float g_inv[BB * SS];

__global__ __launch_bounds__(NT)
void attn_kernel(const float* __restrict__ Q,
                 const float* __restrict__ K,
                 const float* __restrict__ V,
                 float* __restrict__ Ovec,
                 float* __restrict__ W) {
    extern __shared__ float smem[];
    float* sQ = smem;               // [BM][DP]
    float* sK = smem + BM * DP;     // [BN][DP], reused as P tile
    float* sV = smem + 2 * BM * DP; // [BN][DP]

    const int bid   = blockIdx.x;
    const int batch = bid & 3;
    const int tile  = 63 - (bid >> 2);   // descending work: longest rows first
    const int q0    = tile * BM;

    const float* Qb = Q + (size_t)batch * SS * DH;
    const float* Kb = K + (size_t)batch * SS * DH;
    const float* Vb = V + (size_t)batch * SS * DH;

    const int tid = threadIdx.x;
    const int tx  = tid & 15;   // 0..15
    const int ty  = tid >> 4;   // 0..15

    // ---- load Q tile (64x64) ----
    for (int idx = tid * 4; idx < BM * DH; idx += NT * 4) {
        int r = idx >> 6, d = idx & 63;
        float4 v = *reinterpret_cast<const float4*>(Qb + (size_t)(q0 + r) * DH + d);
        *reinterpret_cast<float4*>(&sQ[r * DP + d]) = v;
    }

    float Oacc[4][4];
    #pragma unroll
    for (int i = 0; i < 4; i++)
        #pragma unroll
        for (int j = 0; j < 4; j++) Oacc[i][j] = 0.f;
    float rs[4] = {0.f, 0.f, 0.f, 0.f};

    for (int kt = 0; kt <= tile; kt++) {
        const int k0 = kt * BN;
        __syncthreads();   // previous iteration's sK/sV consumers done
        // ---- load K, V tiles ----
        for (int idx = tid * 4; idx < BN * DH; idx += NT * 4) {
            int r = idx >> 6, d = idx & 63;
            *reinterpret_cast<float4*>(&sK[r * DP + d]) =
                *reinterpret_cast<const float4*>(Kb + (size_t)(k0 + r) * DH + d);
            *reinterpret_cast<float4*>(&sV[r * DP + d]) =
                *reinterpret_cast<const float4*>(Vb + (size_t)(k0 + r) * DH + d);
        }
        __syncthreads();

        // ---- S = Q K^T  (64x64x64), 4x4 micro-tile, strided mapping ----
        float acc[4][4];
        #pragma unroll
        for (int i = 0; i < 4; i++)
            #pragma unroll
            for (int j = 0; j < 4; j++) acc[i][j] = 0.f;

        #pragma unroll
        for (int d = 0; d < DH; d += 4) {
            float4 qv[4], kv[4];
            #pragma unroll
            for (int i = 0; i < 4; i++)
                qv[i] = *reinterpret_cast<float4*>(&sQ[(ty + 16 * i) * DP + d]);
            #pragma unroll
            for (int j = 0; j < 4; j++)
                kv[j] = *reinterpret_cast<float4*>(&sK[(tx + 16 * j) * DP + d]);
            #pragma unroll
            for (int i = 0; i < 4; i++)
                #pragma unroll
                for (int j = 0; j < 4; j++) {
                    acc[i][j] += qv[i].x * kv[j].x;
                    acc[i][j] += qv[i].y * kv[j].y;
                    acc[i][j] += qv[i].z * kv[j].z;
                    acc[i][j] += qv[i].w * kv[j].w;
                }
        }

        __syncthreads();   // done reading sK as K; about to overwrite with P

        // ---- E = exp(S/8) with causal mask; accumulate row sums; stash P in sK ----
        #pragma unroll
        for (int i = 0; i < 4; i++) {
            const int rg = q0 + ty + 16 * i;
            #pragma unroll
            for (int j = 0; j < 4; j++) {
                const int cg = k0 + tx + 16 * j;
                float e = (cg <= rg) ? __expf(acc[i][j] * 0.125f) : 0.f;
                rs[i] += e;
                sK[(ty + 16 * i) * DP + (tx + 16 * j)] = e;
            }
        }
        __syncthreads();

        // ---- write unnormalized E tile to global weights (coalesced float4) ----
        if (W) {
            for (int idx = tid * 4; idx < BM * BN; idx += NT * 4) {
                int r = idx >> 6, c = idx & 63;
                float4 v = *reinterpret_cast<float4*>(&sK[r * DP + c]);
                *reinterpret_cast<float4*>(
                    &W[((size_t)batch * SS + q0 + r) * SS + k0 + c]) = v;
            }
        }

        // ---- O += P @ V ----
        #pragma unroll 8
        for (int k = 0; k < BN; k++) {
            float pv[4], vv[4];
            #pragma unroll
            for (int i = 0; i < 4; i++) pv[i] = sK[(ty + 16 * i) * DP + k];
            #pragma unroll
            for (int j = 0; j < 4; j++) vv[j] = sV[k * DP + tx + 16 * j];
            #pragma unroll
            for (int i = 0; i < 4; i++)
                #pragma unroll
                for (int j = 0; j < 4; j++) Oacc[i][j] += pv[i] * vv[j];
        }
    }

    // ---- reduce row sums across the 16-lane tx group (stays inside warp) ----
    #pragma unroll
    for (int i = 0; i < 4; i++) {
        #pragma unroll
        for (int m = 1; m < 16; m <<= 1)
            rs[i] += __shfl_xor_sync(0xffffffff, rs[i], m);
    }
    float inv[4];
    #pragma unroll
    for (int i = 0; i < 4; i++) inv[i] = 1.f / rs[i];

    // ---- write normalized attention output ----
    #pragma unroll
    for (int i = 0; i < 4; i++) {
        const int rg = q0 + ty + 16 * i;
        #pragma unroll
        for (int j = 0; j < 4; j++)
            Ovec[((size_t)batch * SS + rg) * DH + tx + 16 * j] = Oacc[i][j] * inv[i];
        if (tx == 0) g_inv[batch * SS + rg] = inv[i];
    }
}

// Normalize weights rows by 1/rowsum; zero the masked (k > q) region
// (d_out is poisoned, so the upper triangle must be written explicitly).
__global__ __launch_bounds__(256)
void norm_kernel(float* __restrict__ W) {
    const int row = blockIdx.x;           // 0 .. B*S-1
    const int q   = row & (SS - 1);
    const float inv = g_inv[row];
    float* w = W + (size_t)row * SS;
    for (int k = threadIdx.x; k < SS; k += 256) {
        float val = 0.f;
        if (k <= q) val = w[k] * inv;
        w[k] = val;
    }
}

extern "C" void kernel_launch(void* const* d_in, const int* in_sizes, int n_in,
                              void* d_out, int out_size) {
    const float* Q = (const float*)d_in[0];
    const float* K = (const float*)d_in[1];
    const float* V = (const float*)d_in[2];

    float* Ovec = (float*)d_out;
    float* W = nullptr;
    const long long need = (long long)BB * SS * DH + (long long)BB * SS * SS;
    if ((long long)out_size >= need)
        W = (float*)d_out + (size_t)BB * SS * DH;

    const int smem_bytes = 3 * BM * DP * sizeof(float);   // 52224
    cudaFuncSetAttribute(attn_kernel,
                         cudaFuncAttributeMaxDynamicSharedMemorySize, smem_bytes);

    attn_kernel<<<BB * (SS / BM), NT, smem_bytes>>>(Q, K, V, Ovec, W);
    if (W) norm_kernel<<<BB * SS, 256>>>(W);
}

// round 2
// speedup vs baseline: 2.5995x; 2.5995x over previous
#include <cuda_runtime.h>
#include <cstddef>
#include <cstdint>

#define BB 4
#define SS 4096
#define DH 64
#define BM 64
#define BN 64
#define NT 256
#define DPK 68   // row stride (floats) for sQ/sK/sP: (4*l4+lb) bank map -> conflict-free frags
#define DPV 72   // row stride for sV: (8*lb+l4) bank map -> conflict-free frags

__device__ float g_inv[BB * SS];

__device__ __forceinline__ uint32_t f2tf32(float x) {
    uint32_t r;
    asm("cvt.rna.tf32.f32 %0, %1;" : "=r"(r) : "f"(x));
    return r;
}

__device__ __forceinline__ void mma_tf32(float c[4],
                                         uint32_t a0, uint32_t a1, uint32_t a2, uint32_t a3,
                                         uint32_t b0, uint32_t b1) {
    asm volatile(
        "mma.sync.aligned.m16n8k8.row.col.f32.tf32.tf32.f32 "
        "{%0,%1,%2,%3}, {%4,%5,%6,%7}, {%8,%9}, {%0,%1,%2,%3};"
        : "+f"(c[0]), "+f"(c[1]), "+f"(c[2]), "+f"(c[3])
        : "r"(a0), "r"(a1), "r"(a2), "r"(a3), "r"(b0), "r"(b1));
}

__global__ __launch_bounds__(NT)
void attn_kernel(const float* __restrict__ Q,
                 const float* __restrict__ K,
                 const float* __restrict__ V,
                 float* __restrict__ Ovec,
                 float* __restrict__ W) {
    extern __shared__ float smem[];
    float* sQ  = smem;                      // [64][DPK] tf32 values
    float* sK  = sQ + BM * DPK;             // [64][DPK] tf32 values
    float* sP  = sK + BM * DPK;             // [64][DPK] exact exp values
    float* sV  = sP + BM * DPK;             // [64][DPV] tf32 values
    float* sRS = sV + BM * DPV;             // [64][2] row-sum halves

    const int bid   = blockIdx.x;
    const int batch = bid & 3;
    const int tile  = 63 - (bid >> 2);      // longest causal rows launch first
    const int q0    = tile * BM;

    const float* Qb = Q + (size_t)batch * SS * DH;
    const float* Kb = K + (size_t)batch * SS * DH;
    const float* Vb = V + (size_t)batch * SS * DH;

    const int tid    = threadIdx.x;
    const int lane   = tid & 31;
    const int wid    = tid >> 5;
    const int warp_m = wid & 3;             // 16-row slab
    const int warp_n = wid >> 2;            // 32-col slab
    const int l4     = lane >> 2;           // 0..7
    const int lb     = lane & 3;            // 0..3

    // ---- load Q tile, convert to tf32 ----
    for (int idx = tid * 4; idx < BM * DH; idx += NT * 4) {
        int r = idx >> 6, d = idx & 63;
        float4 v = *reinterpret_cast<const float4*>(Qb + (size_t)(q0 + r) * DH + d);
        float4 o;
        o.x = __uint_as_float(f2tf32(v.x));
        o.y = __uint_as_float(f2tf32(v.y));
        o.z = __uint_as_float(f2tf32(v.z));
        o.w = __uint_as_float(f2tf32(v.w));
        *reinterpret_cast<float4*>(&sQ[r * DPK + d]) = o;
    }
    __syncthreads();

    // ---- Q A-fragments, resident across whole kt loop ----
    const int rm = warp_m * 16;
    uint32_t qa[8][4];
    #pragma unroll
    for (int kc = 0; kc < 8; kc++) {
        qa[kc][0] = __float_as_uint(sQ[(rm + l4) * DPK + kc * 8 + lb]);
        qa[kc][1] = __float_as_uint(sQ[(rm + l4 + 8) * DPK + kc * 8 + lb]);
        qa[kc][2] = __float_as_uint(sQ[(rm + l4) * DPK + kc * 8 + lb + 4]);
        qa[kc][3] = __float_as_uint(sQ[(rm + l4 + 8) * DPK + kc * 8 + lb + 4]);
    }

    float oacc[4][4];
    #pragma unroll
    for (int nt = 0; nt < 4; nt++)
        #pragma unroll
        for (int j = 0; j < 4; j++) oacc[nt][j] = 0.f;
    float rsA = 0.f, rsB = 0.f;

    const int rAg = q0 + rm + l4;           // global rows this thread owns
    const int rBg = rAg + 8;
    const int cnb = warp_n * 32;            // warp's column base inside tile

    for (int kt = 0; kt <= tile; kt++) {
        const int k0 = kt * BN;
        __syncthreads();   // prior iter's sP/sV/sK consumers are done

        // ---- load K, V tiles, convert to tf32 ----
        for (int idx = tid * 4; idx < BN * DH; idx += NT * 4) {
            int r = idx >> 6, d = idx & 63;
            float4 kv = *reinterpret_cast<const float4*>(Kb + (size_t)(k0 + r) * DH + d);
            float4 vv = *reinterpret_cast<const float4*>(Vb + (size_t)(k0 + r) * DH + d);
            float4 ko, vo;
            ko.x = __uint_as_float(f2tf32(kv.x)); ko.y = __uint_as_float(f2tf32(kv.y));
            ko.z = __uint_as_float(f2tf32(kv.z)); ko.w = __uint_as_float(f2tf32(kv.w));
            vo.x = __uint_as_float(f2tf32(vv.x)); vo.y = __uint_as_float(f2tf32(vv.y));
            vo.z = __uint_as_float(f2tf32(vv.z)); vo.w = __uint_as_float(f2tf32(vv.w));
            *reinterpret_cast<float4*>(&sK[r * DPK + d]) = ko;
            *reinterpret_cast<float4*>(&sV[r * DPV + d]) = vo;
        }
        __syncthreads();

        // ---- S = Q K^T on tensor pipe ----
        float sacc[4][4];
        #pragma unroll
        for (int nt = 0; nt < 4; nt++)
            #pragma unroll
            for (int j = 0; j < 4; j++) sacc[nt][j] = 0.f;

        #pragma unroll
        for (int nt = 0; nt < 4; nt++) {
            const int cn = cnb + nt * 8;
            #pragma unroll
            for (int kc = 0; kc < 8; kc++) {
                uint32_t b0 = __float_as_uint(sK[(cn + l4) * DPK + kc * 8 + lb]);
                uint32_t b1 = __float_as_uint(sK[(cn + l4) * DPK + kc * 8 + lb + 4]);
                mma_tf32(sacc[nt], qa[kc][0], qa[kc][1], qa[kc][2], qa[kc][3], b0, b1);
            }
        }

        // ---- mask + exp, stash exact P in sP, accumulate row-sum partials ----
        float prA = 0.f, prB = 0.f;
        #pragma unroll
        for (int nt = 0; nt < 4; nt++) {
            const int cg = k0 + cnb + nt * 8 + 2 * lb;
            float e00 = (cg     <= rAg) ? __expf(sacc[nt][0] * 0.125f) : 0.f;
            float e01 = (cg + 1 <= rAg) ? __expf(sacc[nt][1] * 0.125f) : 0.f;
            float e10 = (cg     <= rBg) ? __expf(sacc[nt][2] * 0.125f) : 0.f;
            float e11 = (cg + 1 <= rBg) ? __expf(sacc[nt][3] * 0.125f) : 0.f;
            prA += e00 + e01;
            prB += e10 + e11;
            float2 vA = make_float2(e00, e01);
            float2 vB = make_float2(e10, e11);
            *reinterpret_cast<float2*>(&sP[(rm + l4) * DPK + cnb + nt * 8 + 2 * lb]) = vA;
            *reinterpret_cast<float2*>(&sP[(rm + l4 + 8) * DPK + cnb + nt * 8 + 2 * lb]) = vB;
        }
        prA += __shfl_xor_sync(0xffffffffu, prA, 1);
        prA += __shfl_xor_sync(0xffffffffu, prA, 2);
        prB += __shfl_xor_sync(0xffffffffu, prB, 1);
        prB += __shfl_xor_sync(0xffffffffu, prB, 2);
        rsA += prA;
        rsB += prB;
        __syncthreads();   // sP tile complete

        // ---- write unnormalized exp tile to W (coalesced float4) ----
        if (W) {
            for (int idx = tid * 4; idx < BM * BN; idx += NT * 4) {
                int r = idx >> 6, c = idx & 63;
                float4 v = *reinterpret_cast<float4*>(&sP[r * DPK + c]);
                *reinterpret_cast<float4*>(
                    &W[((size_t)batch * SS + q0 + r) * SS + k0 + c]) = v;
            }
        }

        // ---- O += P V on tensor pipe ----
        #pragma unroll
        for (int kc = 0; kc < 8; kc++) {
            uint32_t pa0 = f2tf32(sP[(rm + l4) * DPK + kc * 8 + lb]);
            uint32_t pa1 = f2tf32(sP[(rm + l4 + 8) * DPK + kc * 8 + lb]);
            uint32_t pa2 = f2tf32(sP[(rm + l4) * DPK + kc * 8 + lb + 4]);
            uint32_t pa3 = f2tf32(sP[(rm + l4 + 8) * DPK + kc * 8 + lb + 4]);
            #pragma unroll
            for (int nt = 0; nt < 4; nt++) {
                uint32_t b0 = __float_as_uint(sV[(kc * 8 + lb) * DPV + cnb + nt * 8 + l4]);
                uint32_t b1 = __float_as_uint(sV[(kc * 8 + lb + 4) * DPV + cnb + nt * 8 + l4]);
                mma_tf32(oacc[nt], pa0, pa1, pa2, pa3, b0, b1);
            }
        }
    }

    // ---- combine row-sum halves across warp_n via smem ----
    if (lb == 0) {
        sRS[(rm + l4) * 2 + warp_n] = rsA;
        sRS[(rm + l4 + 8) * 2 + warp_n] = rsB;
    }
    __syncthreads();
    const float invA = 1.f / (sRS[(rm + l4) * 2] + sRS[(rm + l4) * 2 + 1]);
    const float invB = 1.f / (sRS[(rm + l4 + 8) * 2] + sRS[(rm + l4 + 8) * 2 + 1]);
    if (warp_n == 0 && lb == 0) {
        g_inv[batch * SS + rAg] = invA;
        g_inv[batch * SS + rBg] = invB;
    }

    // ---- write normalized attention output (float2 per accum pair) ----
    #pragma unroll
    for (int nt = 0; nt < 4; nt++) {
        const int c = cnb + nt * 8 + 2 * lb;
        float2 vA = make_float2(oacc[nt][0] * invA, oacc[nt][1] * invA);
        float2 vB = make_float2(oacc[nt][2] * invB, oacc[nt][3] * invB);
        *reinterpret_cast<float2*>(&Ovec[((size_t)batch * SS + rAg) * DH + c]) = vA;
        *reinterpret_cast<float2*>(&Ovec[((size_t)batch * SS + rBg) * DH + c]) = vB;
    }
}

// Normalize weights rows by 1/rowsum; zero the masked (k > q) region.
// float4 throughout for DRAM efficiency.
__global__ __launch_bounds__(256)
void norm_kernel(float* __restrict__ W) {
    const int row = blockIdx.x;           // 0 .. B*S-1
    const int q   = row & (SS - 1);
    const float inv = g_inv[row];
    float4* w = reinterpret_cast<float4*>(W + (size_t)row * SS);
    #pragma unroll 2
    for (int v = threadIdx.x; v < SS / 4; v += 256) {
        const int k = v * 4;
        float4 out = make_float4(0.f, 0.f, 0.f, 0.f);
        if (k <= q) {
            float4 t = w[v];
            out.x = t.x * inv;
            out.y = (k + 1 <= q) ? t.y * inv : 0.f;
            out.z = (k + 2 <= q) ? t.z * inv : 0.f;
            out.w = (k + 3 <= q) ? t.w * inv : 0.f;
        }
        w[v] = out;
    }
}

extern "C" void kernel_launch(void* const* d_in, const int* in_sizes, int n_in,
                              void* d_out, int out_size) {
    const float* Q = (const float*)d_in[0];
    const float* K = (const float*)d_in[1];
    const float* V = (const float*)d_in[2];

    float* Ovec = (float*)d_out;
    float* W = nullptr;
    const long long need = (long long)BB * SS * DH + (long long)BB * SS * SS;
    if ((long long)out_size >= need)
        W = (float*)d_out + (size_t)BB * SS * DH;

    const int smem_bytes = (3 * BM * DPK + BM * DPV + 128) * sizeof(float); // 71168
    static bool attr_set = false;
    if (!attr_set) {
        cudaFuncSetAttribute(attn_kernel,
                             cudaFuncAttributeMaxDynamicSharedMemorySize, smem_bytes);
        attr_set = true;
    }

    attn_kernel<<<BB * (SS / BM), NT, smem_bytes>>>(Q, K, V, Ovec, W);
    if (W) norm_kernel<<<BB * SS, 256>>>(W);
}

// round 3
// speedup vs baseline: 2.6045x; 1.0019x over previous
#include <cuda_runtime.h>
#include <cstddef>
#include <cstdint>

#define BB 4
#define SS 4096
#define DH 64
#define BM 64
#define BN 64
#define NT 256
#define DPK 68   // row stride (floats) for sQ/sK/sP: (4*l4+lb) bank map -> conflict-free frags
#define DPV 72   // row stride for sV: (8*lb+l4) bank map -> conflict-free frags

__device__ float g_inv[BB * SS];

__device__ __forceinline__ uint32_t f2tf32(float x) {
    uint32_t r;
    asm("cvt.rna.tf32.f32 %0, %1;" : "=r"(r) : "f"(x));
    return r;
}

__device__ __forceinline__ void mma_tf32(float c[4],
                                         uint32_t a0, uint32_t a1, uint32_t a2, uint32_t a3,
                                         uint32_t b0, uint32_t b1) {
    asm volatile(
        "mma.sync.aligned.m16n8k8.row.col.f32.tf32.tf32.f32 "
        "{%0,%1,%2,%3}, {%4,%5,%6,%7}, {%8,%9}, {%0,%1,%2,%3};"
        : "+f"(c[0]), "+f"(c[1]), "+f"(c[2]), "+f"(c[3])
        : "r"(a0), "r"(a1), "r"(a2), "r"(a3), "r"(b0), "r"(b1));
}

__global__ __launch_bounds__(NT)
void attn_kernel(const float* __restrict__ Q,
                 const float* __restrict__ K,
                 const float* __restrict__ V,
                 float* __restrict__ Ovec,
                 float* __restrict__ W) {
    extern __shared__ float smem[];
    float* sQ  = smem;                      // [64][DPK] tf32 values
    float* sK  = sQ + BM * DPK;             // [64][DPK] tf32 values
    float* sP  = sK + BM * DPK;             // [64][DPK] exact exp values
    float* sV  = sP + BM * DPK;             // [64][DPV] tf32 values
    float* sRS = sV + BM * DPV;             // [64][2] row-sum halves

    const int bid   = blockIdx.x;
    const int batch = bid & 3;
    const int tile  = 63 - (bid >> 2);      // longest causal rows launch first
    const int q0    = tile * BM;

    const float* Qb = Q + (size_t)batch * SS * DH;
    const float* Kb = K + (size_t)batch * SS * DH;
    const float* Vb = V + (size_t)batch * SS * DH;

    const int tid    = threadIdx.x;
    const int lane   = tid & 31;
    const int wid    = tid >> 5;
    const int warp_m = wid & 3;             // 16-row slab
    const int warp_n = wid >> 2;            // 32-col slab
    const int l4     = lane >> 2;           // 0..7
    const int lb     = lane & 3;            // 0..3

    // ---- load Q tile, convert to tf32 ----
    for (int idx = tid * 4; idx < BM * DH; idx += NT * 4) {
        int r = idx >> 6, d = idx & 63;
        float4 v = *reinterpret_cast<const float4*>(Qb + (size_t)(q0 + r) * DH + d);
        float4 o;
        o.x = __uint_as_float(f2tf32(v.x));
        o.y = __uint_as_float(f2tf32(v.y));
        o.z = __uint_as_float(f2tf32(v.z));
        o.w = __uint_as_float(f2tf32(v.w));
        *reinterpret_cast<float4*>(&sQ[r * DPK + d]) = o;
    }
    __syncthreads();

    // ---- Q A-fragments, resident across whole kt loop ----
    const int rm = warp_m * 16;
    uint32_t qa[8][4];
    #pragma unroll
    for (int kc = 0; kc < 8; kc++) {
        qa[kc][0] = __float_as_uint(sQ[(rm + l4) * DPK + kc * 8 + lb]);
        qa[kc][1] = __float_as_uint(sQ[(rm + l4 + 8) * DPK + kc * 8 + lb]);
        qa[kc][2] = __float_as_uint(sQ[(rm + l4) * DPK + kc * 8 + lb + 4]);
        qa[kc][3] = __float_as_uint(sQ[(rm + l4 + 8) * DPK + kc * 8 + lb + 4]);
    }

    float oacc[4][4];
    #pragma unroll
    for (int nt = 0; nt < 4; nt++)
        #pragma unroll
        for (int j = 0; j < 4; j++) oacc[nt][j] = 0.f;
    float rsA = 0.f, rsB = 0.f;

    const int rAg = q0 + rm + l4;           // global rows this thread owns
    const int rBg = rAg + 8;
    const int cnb = warp_n * 32;            // warp's column base inside tile

    for (int kt = 0; kt <= tile; kt++) {
        const int k0 = kt * BN;
        __syncthreads();   // prior iter's sP/sV/sK consumers are done

        // ---- load K, V tiles, convert to tf32 ----
        for (int idx = tid * 4; idx < BN * DH; idx += NT * 4) {
            int r = idx >> 6, d = idx & 63;
            float4 kv = *reinterpret_cast<const float4*>(Kb + (size_t)(k0 + r) * DH + d);
            float4 vv = *reinterpret_cast<const float4*>(Vb + (size_t)(k0 + r) * DH + d);
            float4 ko, vo;
            ko.x = __uint_as_float(f2tf32(kv.x)); ko.y = __uint_as_float(f2tf32(kv.y));
            ko.z = __uint_as_float(f2tf32(kv.z)); ko.w = __uint_as_float(f2tf32(kv.w));
            vo.x = __uint_as_float(f2tf32(vv.x)); vo.y = __uint_as_float(f2tf32(vv.y));
            vo.z = __uint_as_float(f2tf32(vv.z)); vo.w = __uint_as_float(f2tf32(vv.w));
            *reinterpret_cast<float4*>(&sK[r * DPK + d]) = ko;
            *reinterpret_cast<float4*>(&sV[r * DPV + d]) = vo;
        }
        __syncthreads();

        // ---- S = Q K^T on tensor pipe ----
        float sacc[4][4];
        #pragma unroll
        for (int nt = 0; nt < 4; nt++)
            #pragma unroll
            for (int j = 0; j < 4; j++) sacc[nt][j] = 0.f;

        #pragma unroll
        for (int nt = 0; nt < 4; nt++) {
            const int cn = cnb + nt * 8;
            #pragma unroll
            for (int kc = 0; kc < 8; kc++) {
                uint32_t b0 = __float_as_uint(sK[(cn + l4) * DPK + kc * 8 + lb]);
                uint32_t b1 = __float_as_uint(sK[(cn + l4) * DPK + kc * 8 + lb + 4]);
                mma_tf32(sacc[nt], qa[kc][0], qa[kc][1], qa[kc][2], qa[kc][3], b0, b1);
            }
        }

        // ---- mask + exp, stash exact P in sP, accumulate row-sum partials ----
        float prA = 0.f, prB = 0.f;
        #pragma unroll
        for (int nt = 0; nt < 4; nt++) {
            const int cg = k0 + cnb + nt * 8 + 2 * lb;
            float e00 = (cg     <= rAg) ? __expf(sacc[nt][0] * 0.125f) : 0.f;
            float e01 = (cg + 1 <= rAg) ? __expf(sacc[nt][1] * 0.125f) : 0.f;
            float e10 = (cg     <= rBg) ? __expf(sacc[nt][2] * 0.125f) : 0.f;
            float e11 = (cg + 1 <= rBg) ? __expf(sacc[nt][3] * 0.125f) : 0.f;
            prA += e00 + e01;
            prB += e10 + e11;
            float2 vA = make_float2(e00, e01);
            float2 vB = make_float2(e10, e11);
            *reinterpret_cast<float2*>(&sP[(rm + l4) * DPK + cnb + nt * 8 + 2 * lb]) = vA;
            *reinterpret_cast<float2*>(&sP[(rm + l4 + 8) * DPK + cnb + nt * 8 + 2 * lb]) = vB;
        }
        prA += __shfl_xor_sync(0xffffffffu, prA, 1);
        prA += __shfl_xor_sync(0xffffffffu, prA, 2);
        prB += __shfl_xor_sync(0xffffffffu, prB, 1);
        prB += __shfl_xor_sync(0xffffffffu, prB, 2);
        rsA += prA;
        rsB += prB;
        __syncthreads();   // sP tile complete

        // ---- write unnormalized exp tile to W (coalesced float4) ----
        if (W) {
            for (int idx = tid * 4; idx < BM * BN; idx += NT * 4) {
                int r = idx >> 6, c = idx & 63;
                float4 v = *reinterpret_cast<float4*>(&sP[r * DPK + c]);
                *reinterpret_cast<float4*>(
                    &W[((size_t)batch * SS + q0 + r) * SS + k0 + c]) = v;
            }
        }

        // ---- O += P V on tensor pipe ----
        #pragma unroll
        for (int kc = 0; kc < 8; kc++) {
            uint32_t pa0 = f2tf32(sP[(rm + l4) * DPK + kc * 8 + lb]);
            uint32_t pa1 = f2tf32(sP[(rm + l4 + 8) * DPK + kc * 8 + lb]);
            uint32_t pa2 = f2tf32(sP[(rm + l4) * DPK + kc * 8 + lb + 4]);
            uint32_t pa3 = f2tf32(sP[(rm + l4 + 8) * DPK + kc * 8 + lb + 4]);
            #pragma unroll
            for (int nt = 0; nt < 4; nt++) {
                uint32_t b0 = __float_as_uint(sV[(kc * 8 + lb) * DPV + cnb + nt * 8 + l4]);
                uint32_t b1 = __float_as_uint(sV[(kc * 8 + lb + 4) * DPV + cnb + nt * 8 + l4]);
                mma_tf32(oacc[nt], pa0, pa1, pa2, pa3, b0, b1);
            }
        }
    }

    // ---- combine row-sum halves across warp_n via smem ----
    if (lb == 0) {
        sRS[(rm + l4) * 2 + warp_n] = rsA;
        sRS[(rm + l4 + 8) * 2 + warp_n] = rsB;
    }
    __syncthreads();
    const float invA = 1.f / (sRS[(rm + l4) * 2] + sRS[(rm + l4) * 2 + 1]);
    const float invB = 1.f / (sRS[(rm + l4 + 8) * 2] + sRS[(rm + l4 + 8) * 2 + 1]);
    if (warp_n == 0 && lb == 0) {
        g_inv[batch * SS + rAg] = invA;
        g_inv[batch * SS + rBg] = invB;
    }

    // ---- write normalized attention output (float2 per accum pair) ----
    #pragma unroll
    for (int nt = 0; nt < 4; nt++) {
        const int c = cnb + nt * 8 + 2 * lb;
        float2 vA = make_float2(oacc[nt][0] * invA, oacc[nt][1] * invA);
        float2 vB = make_float2(oacc[nt][2] * invB, oacc[nt][3] * invB);
        *reinterpret_cast<float2*>(&Ovec[((size_t)batch * SS + rAg) * DH + c]) = vA;
        *reinterpret_cast<float2*>(&Ovec[((size_t)batch * SS + rBg) * DH + c]) = vB;
    }
}

// Normalize weights rows by 1/rowsum; zero the masked (k > q) region.
// float4 throughout for DRAM efficiency.
__global__ __launch_bounds__(256)
void norm_kernel(float* __restrict__ W) {
    const int row = blockIdx.x;           // 0 .. B*S-1
    const int q   = row & (SS - 1);
    const float inv = g_inv[row];
    float4* w = reinterpret_cast<float4*>(W + (size_t)row * SS);
    #pragma unroll 2
    for (int v = threadIdx.x; v < SS / 4; v += 256) {
        const int k = v * 4;
        float4 out = make_float4(0.f, 0.f, 0.f, 0.f);
        if (k <= q) {
            float4 t = w[v];
            out.x = t.x * inv;
            out.y = (k + 1 <= q) ? t.y * inv : 0.f;
            out.z = (k + 2 <= q) ? t.z * inv : 0.f;
            out.w = (k + 3 <= q) ? t.w * inv : 0.f;
        }
        w[v] = out;
    }
}

extern "C" void kernel_launch(void* const* d_in, const int* in_sizes, int n_in,
                              void* d_out, int out_size) {
    const float* Q = (const float*)d_in[0];
    const float* K = (const float*)d_in[1];
    const float* V = (const float*)d_in[2];

    float* Ovec = (float*)d_out;
    float* W = nullptr;
    const long long need = (long long)BB * SS * DH + (long long)BB * SS * SS;
    if ((long long)out_size >= need)
        W = (float*)d_out + (size_t)BB * SS * DH;

    const int smem_bytes = (3 * BM * DPK + BM * DPV + 128) * sizeof(float); // 71168
    static bool attr_set = false;
    if (!attr_set) {
        cudaFuncSetAttribute(attn_kernel,
                             cudaFuncAttributeMaxDynamicSharedMemorySize, smem_bytes);
        attr_set = true;
    }

    attn_kernel<<<BB * (SS / BM), NT, smem_bytes>>>(Q, K, V, Ovec, W);
    if (W) norm_kernel<<<BB * SS, 256>>>(W);
}